// round 16
// baseline (speedup 1.0000x reference)
#include <cuda_runtime.h>
#include <cuda_fp16.h>
#include <mma.h>

using namespace nvcuda;

#define N_NODES_MAX 50000
#define N_EDGES_MAX 800000
#define D 64
#define CAP 128   // bucket capacity per node; Poisson(16) => deg>128 ~impossible

// Scratch (no cudaMalloc allowed). BSS zero at load; kernels re-zero their
// counters after last use each call. g_h1 padded so WMMA tiles can store
// unconditionally past n.
__device__ float g_h1    [(N_NODES_MAX + 128) * D];
__device__ float g_agg   [N_NODES_MAX * D];
__device__ int   g_cnt   [N_NODES_MAX];
__device__ int   g_bucket[N_NODES_MAX * CAP];
__device__ int   g_ovfs  [N_EDGES_MAX];
__device__ int   g_ovfd  [N_EDGES_MAX];
__device__ int   g_novf  [1];

// ---------------------------------------------------------------------------
// Build: one pass. Claim slot in dst's bucket; spill to overflow list if full.
// ---------------------------------------------------------------------------
__global__ void build_kernel(const int* __restrict__ src,
                             const int* __restrict__ dst,
                             int* __restrict__ cnt, int* __restrict__ bucket,
                             int* __restrict__ ovfs, int* __restrict__ ovfd,
                             int* __restrict__ novf, int n_edges) {
    int i = blockIdx.x * blockDim.x + threadIdx.x;
    if (i >= n_edges) return;
    int d = __ldg(dst + i);
    int s = __ldg(src + i);
    int p = atomicAdd(cnt + d, 1);
    if (p < CAP) {
        bucket[(size_t)d * CAP + p] = s;
    } else {
        int q = atomicAdd(novf, 1);
        ovfs[q] = s;
        ovfd[q] = d;
    }
}

// ---------------------------------------------------------------------------
// Gather (lean, R15-proven): warp per node; half-warp per edge (16 x float4).
// ---------------------------------------------------------------------------
__global__ __launch_bounds__(256, 8) void gather_kernel(
    const float* __restrict__ h, const int* __restrict__ bucket,
    int* __restrict__ cnt, float* __restrict__ agg, int n, int clear) {
    int warp = (blockIdx.x * blockDim.x + threadIdx.x) >> 5;
    if (warp >= n) return;
    int lane = threadIdx.x & 31;
    int half = lane >> 4;
    int hl   = lane & 15;
    int o    = warp * CAP;
    int e    = o + min(__ldg(cnt + warp), CAP);
    int last = max(o, e - 1);

    float4 acc = make_float4(0.f, 0.f, 0.f, 0.f);
    for (int i = o + half; i < e; i += 8) {
        int j1 = i + 2, j2 = i + 4, j3 = i + 6;
        int s0 = __ldg(bucket + i);
        int s1 = __ldg(bucket + min(j1, last));
        int s2 = __ldg(bucket + min(j2, last));
        int s3 = __ldg(bucket + min(j3, last));
        float m1 = (j1 < e) ? 1.f : 0.f;
        float m2 = (j2 < e) ? 1.f : 0.f;
        float m3 = (j3 < e) ? 1.f : 0.f;
        float4 v0 = *reinterpret_cast<const float4*>(h + (size_t)s0 * D + hl * 4);
        float4 v1 = *reinterpret_cast<const float4*>(h + (size_t)s1 * D + hl * 4);
        float4 v2 = *reinterpret_cast<const float4*>(h + (size_t)s2 * D + hl * 4);
        float4 v3 = *reinterpret_cast<const float4*>(h + (size_t)s3 * D + hl * 4);
        acc.x += v0.x + m1 * v1.x + m2 * v2.x + m3 * v3.x;
        acc.y += v0.y + m1 * v1.y + m2 * v2.y + m3 * v3.y;
        acc.z += v0.z + m1 * v1.z + m2 * v2.z + m3 * v3.z;
        acc.w += v0.w + m1 * v1.w + m2 * v2.w + m3 * v3.w;
    }
    acc.x += __shfl_down_sync(0xffffffffu, acc.x, 16);
    acc.y += __shfl_down_sync(0xffffffffu, acc.y, 16);
    acc.z += __shfl_down_sync(0xffffffffu, acc.z, 16);
    acc.w += __shfl_down_sync(0xffffffffu, acc.w, 16);
    if (half == 0)
        *reinterpret_cast<float4*>(agg + (size_t)warp * D + hl * 4) = acc;
    if (clear && lane == 0) cnt[warp] = 0;
}

// ---------------------------------------------------------------------------
// Overflow patch-up (novf==0 for sane inputs -> instant exit).
// ---------------------------------------------------------------------------
__global__ __launch_bounds__(256) void overflow_kernel(
    const float* __restrict__ h,
    const int* __restrict__ ovfs, const int* __restrict__ ovfd,
    const int* __restrict__ novf, float* __restrict__ agg) {
    int nov = __ldg(novf);
    for (int j = threadIdx.x; j < nov; j += 256) {
        int s = ovfs[j], d = ovfd[j];
        const float4* hp = reinterpret_cast<const float4*>(h + (size_t)s * D);
        float4* ap = reinterpret_cast<float4*>(agg + (size_t)d * D);
        for (int k = 0; k < 16; k++) atomicAdd(ap + k, hp[k]);
    }
}

// ---------------------------------------------------------------------------
// Stage a 64x64 fp32 tile into fp16 smem (zero-padded rows), 128 threads.
// ---------------------------------------------------------------------------
__device__ __forceinline__ void stage64_f16(
    const float* __restrict__ X, int base, int n, int tid,
    __half (*Xs)[72]) {
    for (int i = tid; i < 64 * 16; i += 128) {
        int r = i >> 4, c4 = i & 15;
        float4 xv = (base + r < n)
            ? *reinterpret_cast<const float4*>(X + (size_t)(base + r) * D + c4 * 4)
            : make_float4(0.f, 0.f, 0.f, 0.f);
        __half2* p = reinterpret_cast<__half2*>(&Xs[r][c4 * 4]);
        p[0] = __floats2half2_rn(xv.x, xv.y);
        p[1] = __floats2half2_rn(xv.z, xv.w);
    }
}

// ---------------------------------------------------------------------------
// Layer-1 GEMM: 64 rows/block, 4 warps. Bias via accumulator-init tiles,
// relu on fragment, direct store_matrix_sync to padded Y. No stage smem.
// ---------------------------------------------------------------------------
__global__ __launch_bounds__(128) void gemm1_wmma(
    const float* __restrict__ X, const float* __restrict__ W,
    const float* __restrict__ b, float* __restrict__ Y, int n) {
    __shared__ __align__(16) __half Xs[64][72];        // 9 KB
    __shared__ __align__(16) __half Ws[64][72];        // 9 KB
    __shared__ __align__(16) float  btile[4][16][16];  // 4 KB
    int tid = threadIdx.x, wid = tid >> 5;
    int base = blockIdx.x * 64;

    for (int i = tid; i < 64 * 64; i += 128)
        Ws[i >> 6][i & 63] = __float2half(W[i]);
    for (int i = tid; i < 4 * 256; i += 128) {
        int nt = i >> 8, c = i & 15;
        btile[nt][(i >> 4) & 15][c] = b[nt * 16 + c];
    }
    stage64_f16(X, base, n, tid, Xs);
    __syncthreads();

    int r0 = wid * 16;
    #pragma unroll
    for (int nt = 0; nt < 4; nt++) {
        wmma::fragment<wmma::accumulator, 16, 16, 16, float> c;
        wmma::load_matrix_sync(c, &btile[nt][0][0], 16, wmma::mem_row_major);
        #pragma unroll
        for (int kt = 0; kt < 4; kt++) {
            wmma::fragment<wmma::matrix_a, 16, 16, 16, half, wmma::row_major> a;
            wmma::fragment<wmma::matrix_b, 16, 16, 16, half, wmma::row_major> bf;
            wmma::load_matrix_sync(a,  &Xs[r0][kt * 16], 72);
            wmma::load_matrix_sync(bf, &Ws[kt * 16][nt * 16], 72);
            wmma::mma_sync(c, a, bf, c);
        }
        #pragma unroll
        for (int t = 0; t < c.num_elements; t++)
            c.x[t] = fmaxf(c.x[t], 0.f);
        // Y padded beyond n: unconditional 16-row store is safe
        wmma::store_matrix_sync(Y + (size_t)(base + r0) * D + nt * 16, c, D,
                                wmma::mem_row_major);
    }
}

// ---------------------------------------------------------------------------
// Layer-2 GEMM + heads: 64 rows/block, 4 warps, static smem (~40 KB).
// h2 via bias-init + staged fp16 conversion; heads via bias-init + staged
// bounded scatter (harness buffers can't be over-stored).
// ---------------------------------------------------------------------------
__global__ __launch_bounds__(128) void gemm2_wmma(
    const float* __restrict__ X, const float* __restrict__ W,
    const float* __restrict__ b,
    const float* __restrict__ Wa, const float* __restrict__ ba,
    const float* __restrict__ Wb, const float* __restrict__ bb,
    float* __restrict__ xa_out, float* __restrict__ xb_out,
    int* __restrict__ novf, int n) {
    __shared__ __align__(16) __half Xs[64][72];         // 9 KB
    __shared__ __align__(16) __half Ws[64][72];         // 9 KB
    __shared__ __align__(16) __half Hs[64][72];         // 9 KB
    __shared__ __align__(16) __half Whs[64][40];        // 5 KB
    __shared__ __align__(16) float  btile[4][16][16];   // 4 KB
    __shared__ __align__(16) float  bhtile[2][16][16];  // 2 KB
    __shared__ __align__(16) float  stage[4][16][16];   // 4 KB
    int tid = threadIdx.x, wid = tid >> 5, lane = tid & 31;
    int base = blockIdx.x * 64;

    if (blockIdx.x == 0 && tid == 0) *novf = 0;   // reset for next call

    for (int i = tid; i < 64 * 64; i += 128)
        Ws[i >> 6][i & 63] = __float2half(W[i]);
    for (int i = tid; i < 64 * 32; i += 128) {
        int k = i >> 5, t = i & 31;
        float wv = (t < 16) ? Wb[k * 16 + t]
                 : (t < 18) ? Wa[k * 2 + (t - 16)] : 0.f;
        if (t < 32) Whs[k][t] = __float2half(wv);
    }
    for (int i = tid; i < 64 * 8; i += 128) {     // zero pad Whs cols 32..39
        int k = i >> 3, t = 32 + (i & 7);
        Whs[k][t] = __float2half(0.f);
    }
    for (int i = tid; i < 4 * 256; i += 128) {
        int nt = i >> 8, c = i & 15;
        btile[nt][(i >> 4) & 15][c] = b[nt * 16 + c];
    }
    for (int i = tid; i < 2 * 256; i += 128) {
        int nt = i >> 8, c = i & 15;
        int t = nt * 16 + c;
        bhtile[nt][(i >> 4) & 15][c] =
            (t < 16) ? bb[t] : (t < 18) ? ba[t - 16] : 0.f;
    }
    stage64_f16(X, base, n, tid, Xs);
    __syncthreads();

    int r0 = wid * 16;
    // h2 = relu(X @ W + b) -> fp16 Hs
    #pragma unroll
    for (int nt = 0; nt < 4; nt++) {
        wmma::fragment<wmma::accumulator, 16, 16, 16, float> c;
        wmma::load_matrix_sync(c, &btile[nt][0][0], 16, wmma::mem_row_major);
        #pragma unroll
        for (int kt = 0; kt < 4; kt++) {
            wmma::fragment<wmma::matrix_a, 16, 16, 16, half, wmma::row_major> a;
            wmma::fragment<wmma::matrix_b, 16, 16, 16, half, wmma::row_major> bf;
            wmma::load_matrix_sync(a,  &Xs[r0][kt * 16], 72);
            wmma::load_matrix_sync(bf, &Ws[kt * 16][nt * 16], 72);
            wmma::mma_sync(c, a, bf, c);
        }
        wmma::store_matrix_sync(&stage[wid][0][0], c, 16, wmma::mem_row_major);
        __syncwarp();
        for (int i = lane; i < 256; i += 32) {
            int rr = i >> 4, cc = i & 15;
            Hs[r0 + rr][nt * 16 + cc] =
                __float2half(fmaxf(stage[wid][rr][cc], 0.f));
        }
        __syncwarp();
    }

    // heads = h2 @ [Wb|Wa|pad] + bh
    #pragma unroll
    for (int nt = 0; nt < 2; nt++) {
        wmma::fragment<wmma::accumulator, 16, 16, 16, float> c;
        wmma::load_matrix_sync(c, &bhtile[nt][0][0], 16, wmma::mem_row_major);
        #pragma unroll
        for (int kt = 0; kt < 4; kt++) {
            wmma::fragment<wmma::matrix_a, 16, 16, 16, half, wmma::row_major> a;
            wmma::fragment<wmma::matrix_b, 16, 16, 16, half, wmma::row_major> bf;
            wmma::load_matrix_sync(a,  &Hs[r0][kt * 16], 72);
            wmma::load_matrix_sync(bf, &Whs[kt * 16][nt * 16], 40);
            wmma::mma_sync(c, a, bf, c);
        }
        wmma::store_matrix_sync(&stage[wid][0][0], c, 16, wmma::mem_row_major);
        __syncwarp();
        for (int i = lane; i < 256; i += 32) {
            int rr = i >> 4, cc = i & 15;
            int t = nt * 16 + cc;
            int grow = base + r0 + rr;
            if (grow < n && t < 18) {
                float vv = stage[wid][rr][cc];
                if (t < 16) xb_out[(size_t)grow * 16 + t] = vv;
                else        xa_out[(size_t)grow * 2 + (t - 16)] = vv;
            }
        }
        __syncwarp();
    }
}

// ---------------------------------------------------------------------------
extern "C" void kernel_launch(void* const* d_in, const int* in_sizes, int n_in,
                              void* d_out, int out_size) {
    const float* v   = (const float*)d_in[0];
    const int*   src = (const int*)  d_in[1];
    const int*   dst = (const int*)  d_in[2];
    const float* W1  = (const float*)d_in[3];
    const float* b1  = (const float*)d_in[4];
    const float* W2  = (const float*)d_in[5];
    const float* b2  = (const float*)d_in[6];
    const float* Wa  = (const float*)d_in[7];
    const float* ba  = (const float*)d_in[8];
    const float* Wb  = (const float*)d_in[9];
    const float* bb  = (const float*)d_in[10];

    int n_nodes = in_sizes[0] / D;
    int n_edges = in_sizes[1];

    float* agg;    cudaGetSymbolAddress((void**)&agg,    g_agg);
    float* h1;     cudaGetSymbolAddress((void**)&h1,     g_h1);
    int*   cnt;    cudaGetSymbolAddress((void**)&cnt,    g_cnt);
    int*   bucket; cudaGetSymbolAddress((void**)&bucket, g_bucket);
    int*   ovfs;   cudaGetSymbolAddress((void**)&ovfs,   g_ovfs);
    int*   ovfd;   cudaGetSymbolAddress((void**)&ovfd,   g_ovfd);
    int*   novf;   cudaGetSymbolAddress((void**)&novf,   g_novf);

    float* xa_out = (float*)d_out;
    float* xb_out = (float*)d_out + (size_t)n_nodes * 2;

    int edge_blocks   = (n_edges + 255) / 256;
    int gather_blocks = (n_nodes * 32 + 255) / 256;
    int wmma_blocks   = (n_nodes + 63) / 64;

    // ---- build ----
    build_kernel<<<edge_blocks, 256>>>(src, dst, cnt, bucket,
                                       ovfs, ovfd, novf, n_edges);

    // ---- Layer 1 ----
    gather_kernel<<<gather_blocks, 256>>>(v, bucket, cnt, agg, n_nodes, 0);
    overflow_kernel<<<1, 256>>>(v, ovfs, ovfd, novf, agg);
    gemm1_wmma<<<wmma_blocks, 128>>>(agg, W1, b1, h1, n_nodes);

    // ---- Layer 2 + heads ----
    gather_kernel<<<gather_blocks, 256>>>(h1, bucket, cnt, agg, n_nodes, 1);
    overflow_kernel<<<1, 256>>>(h1, ovfs, ovfd, novf, agg);
    gemm2_wmma<<<wmma_blocks, 128>>>(agg, W2, b2, Wa, ba, Wb, bb,
                                     xa_out, xb_out, novf, n_nodes);
}

// round 17
// speedup vs baseline: 1.0732x; 1.0732x over previous
#include <cuda_runtime.h>
#include <cuda_fp16.h>
#include <mma.h>

using namespace nvcuda;

#define N_NODES_MAX 50000
#define N_EDGES_MAX 800000
#define D 64
#define CAP 128   // bucket capacity per node; Poisson(16) => deg>128 ~impossible

// Scratch (no cudaMalloc allowed). BSS zero at load; kernels re-zero their
// counters after last use each call. g_h1 padded for unconditional WMMA
// tile stores past n.
__device__ float g_h1    [(N_NODES_MAX + 128) * D];
__device__ float g_agg   [N_NODES_MAX * D];
__device__ int   g_cnt   [N_NODES_MAX];
__device__ int   g_bucket[N_NODES_MAX * CAP];
__device__ int   g_ovfs  [N_EDGES_MAX];
__device__ int   g_ovfd  [N_EDGES_MAX];
__device__ int   g_novf  [1];

// ---------------------------------------------------------------------------
// Build: one pass. Claim slot in dst's bucket; spill to overflow list if full.
// ---------------------------------------------------------------------------
__global__ void build_kernel(const int* __restrict__ src,
                             const int* __restrict__ dst,
                             int* __restrict__ cnt, int* __restrict__ bucket,
                             int* __restrict__ ovfs, int* __restrict__ ovfd,
                             int* __restrict__ novf, int n_edges) {
    int i = blockIdx.x * blockDim.x + threadIdx.x;
    if (i >= n_edges) return;
    int d = __ldg(dst + i);
    int s = __ldg(src + i);
    int p = atomicAdd(cnt + d, 1);
    if (p < CAP) {
        bucket[(size_t)d * CAP + p] = s;
    } else {
        int q = atomicAdd(novf, 1);
        ovfs[q] = s;
        ovfd[q] = d;
    }
}

// ---------------------------------------------------------------------------
// Gather (lean, R15-proven): warp per node; half-warp per edge (16 x float4).
// ---------------------------------------------------------------------------
__global__ __launch_bounds__(256, 8) void gather_kernel(
    const float* __restrict__ h, const int* __restrict__ bucket,
    int* __restrict__ cnt, float* __restrict__ agg, int n, int clear) {
    int warp = (blockIdx.x * blockDim.x + threadIdx.x) >> 5;
    if (warp >= n) return;
    int lane = threadIdx.x & 31;
    int half = lane >> 4;
    int hl   = lane & 15;
    int o    = warp * CAP;
    int e    = o + min(__ldg(cnt + warp), CAP);
    int last = max(o, e - 1);

    float4 acc = make_float4(0.f, 0.f, 0.f, 0.f);
    for (int i = o + half; i < e; i += 8) {
        int j1 = i + 2, j2 = i + 4, j3 = i + 6;
        int s0 = __ldg(bucket + i);
        int s1 = __ldg(bucket + min(j1, last));
        int s2 = __ldg(bucket + min(j2, last));
        int s3 = __ldg(bucket + min(j3, last));
        float m1 = (j1 < e) ? 1.f : 0.f;
        float m2 = (j2 < e) ? 1.f : 0.f;
        float m3 = (j3 < e) ? 1.f : 0.f;
        float4 v0 = *reinterpret_cast<const float4*>(h + (size_t)s0 * D + hl * 4);
        float4 v1 = *reinterpret_cast<const float4*>(h + (size_t)s1 * D + hl * 4);
        float4 v2 = *reinterpret_cast<const float4*>(h + (size_t)s2 * D + hl * 4);
        float4 v3 = *reinterpret_cast<const float4*>(h + (size_t)s3 * D + hl * 4);
        acc.x += v0.x + m1 * v1.x + m2 * v2.x + m3 * v3.x;
        acc.y += v0.y + m1 * v1.y + m2 * v2.y + m3 * v3.y;
        acc.z += v0.z + m1 * v1.z + m2 * v2.z + m3 * v3.z;
        acc.w += v0.w + m1 * v1.w + m2 * v2.w + m3 * v3.w;
    }
    acc.x += __shfl_down_sync(0xffffffffu, acc.x, 16);
    acc.y += __shfl_down_sync(0xffffffffu, acc.y, 16);
    acc.z += __shfl_down_sync(0xffffffffu, acc.z, 16);
    acc.w += __shfl_down_sync(0xffffffffu, acc.w, 16);
    if (half == 0)
        *reinterpret_cast<float4*>(agg + (size_t)warp * D + hl * 4) = acc;
    if (clear && lane == 0) cnt[warp] = 0;
}

// ---------------------------------------------------------------------------
// Overflow patch-up (novf==0 for sane inputs -> instant exit).
// ---------------------------------------------------------------------------
__global__ __launch_bounds__(256) void overflow_kernel(
    const float* __restrict__ h,
    const int* __restrict__ ovfs, const int* __restrict__ ovfd,
    const int* __restrict__ novf, float* __restrict__ agg) {
    int nov = __ldg(novf);
    for (int j = threadIdx.x; j < nov; j += 256) {
        int s = ovfs[j], d = ovfd[j];
        const float4* hp = reinterpret_cast<const float4*>(h + (size_t)s * D);
        float4* ap = reinterpret_cast<float4*>(agg + (size_t)d * D);
        for (int k = 0; k < 16; k++) atomicAdd(ap + k, hp[k]);
    }
}

// ---------------------------------------------------------------------------
// Stage a 128x64 fp32 tile into fp16 smem (zero-padded rows), 256 threads.
// ---------------------------------------------------------------------------
__device__ __forceinline__ void stage_tile_f16(
    const float* __restrict__ X, int base, int n, int tid,
    __half (*Xs)[72]) {
    for (int i = tid; i < 128 * 16; i += 256) {
        int r = i >> 4, c4 = i & 15;
        float4 xv = (base + r < n)
            ? *reinterpret_cast<const float4*>(X + (size_t)(base + r) * D + c4 * 4)
            : make_float4(0.f, 0.f, 0.f, 0.f);
        __half2* p = reinterpret_cast<__half2*>(&Xs[r][c4 * 4]);
        p[0] = __floats2half2_rn(xv.x, xv.y);
        p[1] = __floats2half2_rn(xv.z, xv.w);
    }
}

// ---------------------------------------------------------------------------
// Layer-1 GEMM (R15 tiling + R16 epilogue): 128 rows/block, 8 warps.
// Bias via accumulator-init tiles, relu on fragment, direct store to padded Y.
// ---------------------------------------------------------------------------
__global__ __launch_bounds__(256) void gemm1_wmma(
    const float* __restrict__ X, const float* __restrict__ W,
    const float* __restrict__ b, float* __restrict__ Y, int n) {
    __shared__ __align__(16) __half Xs[128][72];       // 18 KB
    __shared__ __align__(16) __half Ws[64][72];        // 9 KB
    __shared__ __align__(16) float  btile[4][16][16];  // 4 KB
    int tid = threadIdx.x, wid = tid >> 5;
    int base = blockIdx.x * 128;

    for (int i = tid; i < 64 * 64; i += 256)
        Ws[i >> 6][i & 63] = __float2half(W[i]);
    for (int i = tid; i < 4 * 256; i += 256) {
        int nt = i >> 8, c = i & 15;
        btile[nt][(i >> 4) & 15][c] = b[nt * 16 + c];
    }
    stage_tile_f16(X, base, n, tid, Xs);
    __syncthreads();

    int r0 = wid * 16;
    #pragma unroll
    for (int nt = 0; nt < 4; nt++) {
        wmma::fragment<wmma::accumulator, 16, 16, 16, float> c;
        wmma::load_matrix_sync(c, &btile[nt][0][0], 16, wmma::mem_row_major);
        #pragma unroll
        for (int kt = 0; kt < 4; kt++) {
            wmma::fragment<wmma::matrix_a, 16, 16, 16, half, wmma::row_major> a;
            wmma::fragment<wmma::matrix_b, 16, 16, 16, half, wmma::row_major> bf;
            wmma::load_matrix_sync(a,  &Xs[r0][kt * 16], 72);
            wmma::load_matrix_sync(bf, &Ws[kt * 16][nt * 16], 72);
            wmma::mma_sync(c, a, bf, c);
        }
        #pragma unroll
        for (int t = 0; t < c.num_elements; t++)
            c.x[t] = fmaxf(c.x[t], 0.f);
        // Y padded beyond n: unconditional 16-row tile store is safe
        wmma::store_matrix_sync(Y + (size_t)(base + r0) * D + nt * 16, c, D,
                                wmma::mem_row_major);
    }
}

// ---------------------------------------------------------------------------
// Layer-2 GEMM + heads (R15-proven structure, bias-init accumulators).
// ---------------------------------------------------------------------------
struct S2 {
    __half Xs[128][72];
    __half Ws[64][72];
    __half Hs[128][72];
    __half Whs[64][40];
    float  stage[8][16][16];
    float  btile[4][16][16];
    float  bhtile[2][16][16];
};

__global__ __launch_bounds__(256) void gemm2_wmma(
    const float* __restrict__ X, const float* __restrict__ W,
    const float* __restrict__ b,
    const float* __restrict__ Wa, const float* __restrict__ ba,
    const float* __restrict__ Wb, const float* __restrict__ bb,
    float* __restrict__ xa_out, float* __restrict__ xb_out,
    int* __restrict__ novf, int n) {
    extern __shared__ __align__(16) char smem2[];
    S2* s = reinterpret_cast<S2*>(smem2);
    int tid = threadIdx.x, wid = tid >> 5, lane = tid & 31;
    int base = blockIdx.x * 128;

    if (blockIdx.x == 0 && tid == 0) *novf = 0;   // reset for next call

    for (int i = tid; i < 64 * 64; i += 256)
        s->Ws[i >> 6][i & 63] = __float2half(W[i]);
    for (int i = tid; i < 64 * 40; i += 256) {
        int k = i / 40, t = i % 40;
        float wv = (t < 16) ? Wb[k * 16 + t]
                 : (t < 18) ? Wa[k * 2 + (t - 16)] : 0.f;
        s->Whs[k][t] = __float2half(wv);
    }
    for (int i = tid; i < 4 * 256; i += 256) {
        int nt = i >> 8, c = i & 15;
        s->btile[nt][(i >> 4) & 15][c] = b[nt * 16 + c];
    }
    for (int i = tid; i < 2 * 256; i += 256) {
        int nt = i >> 8, c = i & 15;
        int t = nt * 16 + c;
        s->bhtile[nt][(i >> 4) & 15][c] =
            (t < 16) ? bb[t] : (t < 18) ? ba[t - 16] : 0.f;
    }
    stage_tile_f16(X, base, n, tid, s->Xs);
    __syncthreads();

    int r0 = wid * 16;
    // h2 = relu(X @ W + b) -> fp16 Hs
    #pragma unroll
    for (int nt = 0; nt < 4; nt++) {
        wmma::fragment<wmma::accumulator, 16, 16, 16, float> c;
        wmma::load_matrix_sync(c, &s->btile[nt][0][0], 16, wmma::mem_row_major);
        #pragma unroll
        for (int kt = 0; kt < 4; kt++) {
            wmma::fragment<wmma::matrix_a, 16, 16, 16, half, wmma::row_major> a;
            wmma::fragment<wmma::matrix_b, 16, 16, 16, half, wmma::row_major> bf;
            wmma::load_matrix_sync(a,  &s->Xs[r0][kt * 16], 72);
            wmma::load_matrix_sync(bf, &s->Ws[kt * 16][nt * 16], 72);
            wmma::mma_sync(c, a, bf, c);
        }
        wmma::store_matrix_sync(&s->stage[wid][0][0], c, 16, wmma::mem_row_major);
        __syncwarp();
        for (int i = lane; i < 256; i += 32) {
            int rr = i >> 4, cc = i & 15;
            s->Hs[r0 + rr][nt * 16 + cc] =
                __float2half(fmaxf(s->stage[wid][rr][cc], 0.f));
        }
        __syncwarp();
    }

    // heads = h2 @ [Wb|Wa|pad] + bh
    #pragma unroll
    for (int nt = 0; nt < 2; nt++) {
        wmma::fragment<wmma::accumulator, 16, 16, 16, float> c;
        wmma::load_matrix_sync(c, &s->bhtile[nt][0][0], 16, wmma::mem_row_major);
        #pragma unroll
        for (int kt = 0; kt < 4; kt++) {
            wmma::fragment<wmma::matrix_a, 16, 16, 16, half, wmma::row_major> a;
            wmma::fragment<wmma::matrix_b, 16, 16, 16, half, wmma::row_major> bf;
            wmma::load_matrix_sync(a,  &s->Hs[r0][kt * 16], 72);
            wmma::load_matrix_sync(bf, &s->Whs[kt * 16][nt * 16], 40);
            wmma::mma_sync(c, a, bf, c);
        }
        wmma::store_matrix_sync(&s->stage[wid][0][0], c, 16, wmma::mem_row_major);
        __syncwarp();
        for (int i = lane; i < 256; i += 32) {
            int rr = i >> 4, cc = i & 15;
            int t = nt * 16 + cc;
            int grow = base + r0 + rr;
            if (grow < n && t < 18) {
                float vv = s->stage[wid][rr][cc];
                if (t < 16) xb_out[(size_t)grow * 16 + t] = vv;
                else        xa_out[(size_t)grow * 2 + (t - 16)] = vv;
            }
        }
        __syncwarp();
    }
}

// ---------------------------------------------------------------------------
extern "C" void kernel_launch(void* const* d_in, const int* in_sizes, int n_in,
                              void* d_out, int out_size) {
    const float* v   = (const float*)d_in[0];
    const int*   src = (const int*)  d_in[1];
    const int*   dst = (const int*)  d_in[2];
    const float* W1  = (const float*)d_in[3];
    const float* b1  = (const float*)d_in[4];
    const float* W2  = (const float*)d_in[5];
    const float* b2  = (const float*)d_in[6];
    const float* Wa  = (const float*)d_in[7];
    const float* ba  = (const float*)d_in[8];
    const float* Wb  = (const float*)d_in[9];
    const float* bb  = (const float*)d_in[10];

    int n_nodes = in_sizes[0] / D;
    int n_edges = in_sizes[1];

    float* agg;    cudaGetSymbolAddress((void**)&agg,    g_agg);
    float* h1;     cudaGetSymbolAddress((void**)&h1,     g_h1);
    int*   cnt;    cudaGetSymbolAddress((void**)&cnt,    g_cnt);
    int*   bucket; cudaGetSymbolAddress((void**)&bucket, g_bucket);
    int*   ovfs;   cudaGetSymbolAddress((void**)&ovfs,   g_ovfs);
    int*   ovfd;   cudaGetSymbolAddress((void**)&ovfd,   g_ovfd);
    int*   novf;   cudaGetSymbolAddress((void**)&novf,   g_novf);

    float* xa_out = (float*)d_out;
    float* xb_out = (float*)d_out + (size_t)n_nodes * 2;

    int edge_blocks   = (n_edges + 255) / 256;
    int gather_blocks = (n_nodes * 32 + 255) / 256;
    int wmma_blocks   = (n_nodes + 127) / 128;

    static_assert(sizeof(S2) < 96 * 1024, "smem overflow");
    cudaFuncSetAttribute(gemm2_wmma,
                         cudaFuncAttributeMaxDynamicSharedMemorySize,
                         (int)sizeof(S2));

    // ---- build ----
    build_kernel<<<edge_blocks, 256>>>(src, dst, cnt, bucket,
                                       ovfs, ovfd, novf, n_edges);

    // ---- Layer 1 ----
    gather_kernel<<<gather_blocks, 256>>>(v, bucket, cnt, agg, n_nodes, 0);
    overflow_kernel<<<1, 256>>>(v, ovfs, ovfd, novf, agg);
    gemm1_wmma<<<wmma_blocks, 256>>>(agg, W1, b1, h1, n_nodes);

    // ---- Layer 2 + heads ----
    gather_kernel<<<gather_blocks, 256>>>(h1, bucket, cnt, agg, n_nodes, 1);
    overflow_kernel<<<1, 256>>>(h1, ovfs, ovfd, novf, agg);
    gemm2_wmma<<<wmma_blocks, 256, sizeof(S2)>>>(agg, W2, b2, Wa, ba, Wb, bb,
                                                 xa_out, xb_out, novf, n_nodes);
}